// round 2
// baseline (speedup 1.0000x reference)
#include <cuda_runtime.h>
#include <cstdint>
#include <math.h>

#define N_NODES 55296
#define N_EDGES 221184
#define HID 32

// ---------------- device scratch (allocation-free rule: static globals) ------
__device__ float g_We[(size_t)N_EDGES * 1024];   // [E][h][o] fp32, 906 MB
__device__ float g_S[2 * N_NODES * HID];         // node/hidden state [B,N,H]
__device__ float g_agg[2 * N_NODES * HID];       // scatter accumulator

// ---------------- packed f32x2 helpers ---------------------------------------
__device__ __forceinline__ unsigned long long pk2(float x, float y) {
    unsigned long long r;
    asm("mov.b64 %0, {%1, %2};" : "=l"(r) : "f"(x), "f"(y));
    return r;
}
__device__ __forceinline__ void fma2(unsigned long long& c,
                                     unsigned long long a, unsigned long long b) {
    asm("fma.rn.f32x2 %0, %1, %2, %0;" : "+l"(c) : "l"(a), "l"(b));
}
__device__ __forceinline__ void unpk2(unsigned long long d, float& x, float& y) {
    asm("mov.b64 {%0, %1}, %2;" : "=f"(x), "=f"(y) : "l"(d));
}

// ---------------- h0 = relu(x@pw1+pb1)@pw2+pb2  (warp per node) ---------------
__global__ __launch_bounds__(256) void k_h0(const float* __restrict__ x,
        const float* __restrict__ pw1, const float* __restrict__ pb1,
        const float* __restrict__ pw2, const float* __restrict__ pb2) {
    __shared__ float s_w1[1024], s_w2[1024], s_b1[32], s_b2[32];
    int tid = threadIdx.x;
    for (int i = tid; i < 1024; i += 256) { s_w1[i] = pw1[i]; s_w2[i] = pw2[i]; }
    if (tid < 32) { s_b1[tid] = pb1[tid]; s_b2[tid] = pb2[tid]; }
    __syncthreads();
    int w = blockIdx.x * 8 + (tid >> 5);    // over 2*N nodes
    int lane = tid & 31;
    float xv = x[w * 32 + lane];
    float acc = s_b1[lane];
    #pragma unroll
    for (int k = 0; k < 32; k++)
        acc = fmaf(__shfl_sync(0xffffffffu, xv, k), s_w1[k * 32 + lane], acc);
    acc = fmaxf(acc, 0.f);
    float acc2 = s_b2[lane];
    #pragma unroll
    for (int k = 0; k < 32; k++)
        acc2 = fmaf(__shfl_sync(0xffffffffu, acc, k), s_w2[k * 32 + lane], acc2);
    g_S[w * 32 + lane] = acc2;
}

// ---------------- We = (relu(erel@ew1+eb1)@ew2+eb2)  -> g_We ------------------
// 128 edges per block, 256 threads: thread tile = 8 edges x 4 j, f32x2 FMAs.
__global__ __launch_bounds__(256) void k_We(const float* __restrict__ erel,
        const float* __restrict__ ew1, const float* __restrict__ eb1,
        const float* __restrict__ ew2, const float* __restrict__ eb2) {
    __shared__ float s_A[32 * 128];   // h_e, k-major: s_A[k*128+e]
    __shared__ float s_B[32 * 256];   // ew2 chunk:   s_B[k*256+jj]
    int tid = threadIdx.x;
    int e0 = blockIdx.x * 128;

    if (tid < 128) {
        float4 rel = *(const float4*)(erel + (size_t)(e0 + tid) * 4);
        #pragma unroll
        for (int k = 0; k < 32; k++) {
            float v = __ldg(eb1 + k)
                    + rel.x * __ldg(ew1 + k)       + rel.y * __ldg(ew1 + 32 + k)
                    + rel.z * __ldg(ew1 + 64 + k)  + rel.w * __ldg(ew1 + 96 + k);
            s_A[k * 128 + tid] = fmaxf(v, 0.f);
        }
    }

    int es = tid >> 6;        // 0..3  -> edge strip of 32
    int js = tid & 63;        // 0..63 -> 4 consecutive j
    int j0 = js << 2;

    for (int c = 0; c < 4; c++) {
        __syncthreads();
        #pragma unroll
        for (int i = 0; i < 8; i++) {
            int f  = tid + i * 256;        // 0..2047 float4 slots
            int k  = f >> 6;
            int jj = (f & 63) << 2;
            *(float4*)&s_B[k * 256 + jj] =
                *(const float4*)(ew2 + (size_t)k * 1024 + c * 256 + jj);
        }
        __syncthreads();

        int jglob = c * 256 + j0;
        float4 bias = *(const float4*)(eb2 + jglob);
        unsigned long long bias01 = pk2(bias.x, bias.y);
        unsigned long long bias23 = pk2(bias.z, bias.w);

        #pragma unroll
        for (int g = 0; g < 4; g++) {
            int eb = es * 32 + g * 8;
            unsigned long long acc[8][2];
            #pragma unroll
            for (int i = 0; i < 8; i++) { acc[i][0] = bias01; acc[i][1] = bias23; }

            #pragma unroll 8
            for (int k = 0; k < 32; k++) {
                float4 a03 = *(float4*)&s_A[k * 128 + eb];
                float4 a47 = *(float4*)&s_A[k * 128 + eb + 4];
                float4 b   = *(float4*)&s_B[k * 256 + j0];
                unsigned long long b01 = pk2(b.x, b.y);
                unsigned long long b23 = pk2(b.z, b.w);
                unsigned long long a;
                a = pk2(a03.x, a03.x); fma2(acc[0][0], a, b01); fma2(acc[0][1], a, b23);
                a = pk2(a03.y, a03.y); fma2(acc[1][0], a, b01); fma2(acc[1][1], a, b23);
                a = pk2(a03.z, a03.z); fma2(acc[2][0], a, b01); fma2(acc[2][1], a, b23);
                a = pk2(a03.w, a03.w); fma2(acc[3][0], a, b01); fma2(acc[3][1], a, b23);
                a = pk2(a47.x, a47.x); fma2(acc[4][0], a, b01); fma2(acc[4][1], a, b23);
                a = pk2(a47.y, a47.y); fma2(acc[5][0], a, b01); fma2(acc[5][1], a, b23);
                a = pk2(a47.z, a47.z); fma2(acc[6][0], a, b01); fma2(acc[6][1], a, b23);
                a = pk2(a47.w, a47.w); fma2(acc[7][0], a, b01); fma2(acc[7][1], a, b23);
            }
            #pragma unroll
            for (int i = 0; i < 8; i++) {
                float4 o;
                unpk2(acc[i][0], o.x, o.y);
                unpk2(acc[i][1], o.z, o.w);
                *(float4*)(g_We + (size_t)(e0 + eb + i) * 1024 + jglob) = o;
            }
        }
    }
}

// ---------------- agg init: agg[b,n,o] = conv_b[o] ----------------------------
__global__ __launch_bounds__(256) void k_agginit(const float* __restrict__ conv_b) {
    int i = blockIdx.x * 256 + threadIdx.x;
    g_agg[i] = __ldg(conv_b + (i & 31));
}

// ---------------- message + scatter (warp per edge, both batches) -------------
__global__ __launch_bounds__(256) void k_msg(const int* __restrict__ esrc,
                                             const int* __restrict__ edst) {
    int w = blockIdx.x * 8 + (threadIdx.x >> 5);
    int lane = threadIdx.x & 31;
    int src = __ldg(esrc + w);
    int dst = __ldg(edst + w);
    float v0 = g_S[src * 32 + lane];
    float v1 = g_S[(N_NODES + src) * 32 + lane];
    const float* Wp = g_We + (size_t)w * 1024;
    float m0 = 0.f, m1 = 0.f;
    #pragma unroll 8
    for (int h = 0; h < 32; h++) {
        float wv = __ldg(Wp + h * 32 + lane);
        m0 = fmaf(__shfl_sync(0xffffffffu, v0, h), wv, m0);
        m1 = fmaf(__shfl_sync(0xffffffffu, v1, h), wv, m1);
    }
    atomicAdd(&g_agg[dst * 32 + lane], m0);
    atomicAdd(&g_agg[(N_NODES + dst) * 32 + lane], m1);
}

// ---------------- ReLU + single GRU step (warp per node) ----------------------
__global__ __launch_bounds__(256) void k_gru(const float* __restrict__ wih,
        const float* __restrict__ whh, const float* __restrict__ bih,
        const float* __restrict__ bhh, float* __restrict__ out, int writeOut) {
    __shared__ float s_ih[32 * 96];   // [h][i] transposed
    __shared__ float s_hh[32 * 96];
    int tid = threadIdx.x;
    for (int idx = tid; idx < 3072; idx += 256) {
        int i = idx >> 5, h = idx & 31;
        s_ih[h * 96 + i] = wih[idx];
        s_hh[h * 96 + i] = whh[idx];
    }
    __syncthreads();
    int w = blockIdx.x * 8 + (tid >> 5);   // over 2*N nodes
    int lane = tid & 31;
    float nv = fmaxf(g_agg[w * 32 + lane], 0.f);
    float hv = g_S[w * 32 + lane];
    float gxr = __ldg(bih + lane), gxz = __ldg(bih + 32 + lane), gxn = __ldg(bih + 64 + lane);
    float ghr = __ldg(bhh + lane), ghz = __ldg(bhh + 32 + lane), ghn = __ldg(bhh + 64 + lane);
    #pragma unroll
    for (int h = 0; h < 32; h++) {
        float a = __shfl_sync(0xffffffffu, nv, h);
        float b = __shfl_sync(0xffffffffu, hv, h);
        const float* pi = s_ih + h * 96;
        const float* ph = s_hh + h * 96;
        gxr = fmaf(a, pi[lane], gxr);
        gxz = fmaf(a, pi[32 + lane], gxz);
        gxn = fmaf(a, pi[64 + lane], gxn);
        ghr = fmaf(b, ph[lane], ghr);
        ghz = fmaf(b, ph[32 + lane], ghz);
        ghn = fmaf(b, ph[64 + lane], ghn);
    }
    float r  = 1.f / (1.f + expf(-(gxr + ghr)));
    float z  = 1.f / (1.f + expf(-(gxz + ghz)));
    float nn = tanhf(gxn + r * ghn);
    float newh = (1.f - z) * nn + z * hv;
    g_S[w * 32 + lane] = newh;
    if (writeOut) out[w * 32 + lane] = newh;
}

// ---------------- launch ------------------------------------------------------
extern "C" void kernel_launch(void* const* d_in, const int* in_sizes, int n_in,
                              void* d_out, int out_size) {
    const float* x     = (const float*)d_in[0];
    const float* erel  = (const float*)d_in[1];
    const float* pw1   = (const float*)d_in[2];
    const float* pb1   = (const float*)d_in[3];
    const float* pw2   = (const float*)d_in[4];
    const float* pb2   = (const float*)d_in[5];
    const float* ew1   = (const float*)d_in[6];
    const float* eb1   = (const float*)d_in[7];
    const float* ew2   = (const float*)d_in[8];
    const float* eb2   = (const float*)d_in[9];
    const float* convb = (const float*)d_in[10];
    const float* wih   = (const float*)d_in[11];
    const float* whh   = (const float*)d_in[12];
    const float* bih   = (const float*)d_in[13];
    const float* bhh   = (const float*)d_in[14];
    const int*   esrc  = (const int*)d_in[15];
    const int*   edst  = (const int*)d_in[16];
    float* out = (float*)d_out;

    k_h0<<<2 * N_NODES / 8, 256>>>(x, pw1, pb1, pw2, pb2);
    k_We<<<N_EDGES / 128, 256>>>(erel, ew1, eb1, ew2, eb2);
    for (int s = 0; s < 3; s++) {
        k_agginit<<<2 * N_NODES * HID / 256, 256>>>(convb);
        k_msg<<<N_EDGES / 8, 256>>>(esrc, edst);
        k_gru<<<2 * N_NODES / 8, 256>>>(wih, whh, bih, bhh, out, s == 2);
    }
}

// round 4
// speedup vs baseline: 1.0591x; 1.0591x over previous
#include <cuda_runtime.h>
#include <cuda_fp16.h>
#include <cstdint>
#include <math.h>

#define N_NODES 55296
#define N_EDGES 221184
#define HID 32

// ---------------- device scratch (allocation-free rule: static globals) ------
__device__ __half g_We_h[(size_t)N_EDGES * 1024]; // [E][o][h] fp16 transposed, 453 MB
__device__ float  g_ew2t[32 * 1024];              // ew2 permuted: [k][o*32+h]
__device__ float  g_S[2 * N_NODES * HID];         // node/hidden state [B,N,H]
__device__ float  g_agg[2 * N_NODES * HID];       // scatter accumulator

// ---------------- tf32 helpers ------------------------------------------------
__device__ __forceinline__ unsigned tf32hi(float x) {
    unsigned r;
    asm("cvt.rna.tf32.f32 %0, %1;" : "=r"(r) : "f"(x));
    return r;
}
__device__ __forceinline__ void mma_tf32(float& c0, float& c1, float& c2, float& c3,
        unsigned a0, unsigned a1, unsigned a2, unsigned a3,
        unsigned b0, unsigned b1) {
    asm volatile(
        "mma.sync.aligned.m16n8k8.row.col.f32.tf32.tf32.f32 "
        "{%0,%1,%2,%3}, {%4,%5,%6,%7}, {%8,%9}, {%0,%1,%2,%3};\n"
        : "+f"(c0), "+f"(c1), "+f"(c2), "+f"(c3)
        : "r"(a0), "r"(a1), "r"(a2), "r"(a3), "r"(b0), "r"(b1));
}

// ---------------- ew2 transpose: g_ew2t[k][o*32+h] = ew2[k][h*32+o] -----------
__global__ __launch_bounds__(256) void k_tr(const float* __restrict__ ew2) {
    int i = blockIdx.x * 256 + threadIdx.x;      // output index, coalesced write
    int k = i >> 10, j = i & 1023;               // j = o*32 + h
    int o = j >> 5, h = j & 31;
    g_ew2t[i] = ew2[k * 1024 + h * 32 + o];
}

// ---------------- h0 = relu(x@pw1+pb1)@pw2+pb2  (warp per node) ---------------
__global__ __launch_bounds__(256) void k_h0(const float* __restrict__ x,
        const float* __restrict__ pw1, const float* __restrict__ pb1,
        const float* __restrict__ pw2, const float* __restrict__ pb2) {
    __shared__ float s_w1[1024], s_w2[1024], s_b1[32], s_b2[32];
    int tid = threadIdx.x;
    for (int i = tid; i < 1024; i += 256) { s_w1[i] = pw1[i]; s_w2[i] = pw2[i]; }
    if (tid < 32) { s_b1[tid] = pb1[tid]; s_b2[tid] = pb2[tid]; }
    __syncthreads();
    int w = blockIdx.x * 8 + (tid >> 5);    // over 2*N nodes
    int lane = tid & 31;
    float xv = x[w * 32 + lane];
    float acc = s_b1[lane];
    #pragma unroll
    for (int k = 0; k < 32; k++)
        acc = fmaf(__shfl_sync(0xffffffffu, xv, k), s_w1[k * 32 + lane], acc);
    acc = fmaxf(acc, 0.f);
    float acc2 = s_b2[lane];
    #pragma unroll
    for (int k = 0; k < 32; k++)
        acc2 = fmaf(__shfl_sync(0xffffffffu, acc, k), s_w2[k * 32 + lane], acc2);
    g_S[w * 32 + lane] = acc2;
}

// ---------------- We^T via 3xTF32 tensor-core GEMM -> g_We_h (fp16) -----------
// Block: 256 thr / 8 warps, 128 edges. Warp = 16 edges x full N (8 chunks x 128).
__global__ __launch_bounds__(256) void k_We(const float* __restrict__ erel,
        const float* __restrict__ ew1, const float* __restrict__ eb1,
        const float* __restrict__ eb2) {
    __shared__ float s_A[128 * 33];    // he, [e][k] fp32, pad 33
    __shared__ float s_B[32 * 136];    // ew2t chunk [k][n] fp32, pad 136
    int tid = threadIdx.x;
    int e0 = blockIdx.x * 128;

    // stage 1: he = relu(rel @ ew1 + eb1)
    if (tid < 128) {
        float4 rel = *(const float4*)(erel + (size_t)(e0 + tid) * 4);
        #pragma unroll
        for (int k = 0; k < 32; k++) {
            float v = __ldg(eb1 + k)
                    + rel.x * __ldg(ew1 + k)       + rel.y * __ldg(ew1 + 32 + k)
                    + rel.z * __ldg(ew1 + 64 + k)  + rel.w * __ldg(ew1 + 96 + k);
            s_A[tid * 33 + k] = fmaxf(v, 0.f);
        }
    }
    __syncthreads();

    // build A fragments (hi/lo) once per warp: 16 edges x 32 k
    int w    = tid >> 5;
    int lane = tid & 31;
    int tm4  = lane & 3;
    int td4  = lane >> 2;
    int ebL  = w * 16;
    unsigned Ahi[4][4], Alo[4][4];
    #pragma unroll
    for (int ks = 0; ks < 4; ks++) {
        int k0 = ks * 8;
        float a0 = s_A[(ebL + td4)     * 33 + k0 + tm4];
        float a1 = s_A[(ebL + td4 + 8) * 33 + k0 + tm4];
        float a2 = s_A[(ebL + td4)     * 33 + k0 + tm4 + 4];
        float a3 = s_A[(ebL + td4 + 8) * 33 + k0 + tm4 + 4];
        Ahi[ks][0] = tf32hi(a0); Alo[ks][0] = __float_as_uint(a0 - __uint_as_float(Ahi[ks][0]));
        Ahi[ks][1] = tf32hi(a1); Alo[ks][1] = __float_as_uint(a1 - __uint_as_float(Ahi[ks][1]));
        Ahi[ks][2] = tf32hi(a2); Alo[ks][2] = __float_as_uint(a2 - __uint_as_float(Ahi[ks][2]));
        Ahi[ks][3] = tf32hi(a3); Alo[ks][3] = __float_as_uint(a3 - __uint_as_float(Ahi[ks][3]));
    }

    for (int c = 0; c < 8; c++) {
        if (c) __syncthreads();
        #pragma unroll
        for (int i = 0; i < 16; i++) {
            int idx = tid + i * 256;
            int k = idx >> 7, n = idx & 127;
            s_B[k * 136 + n] = g_ew2t[k * 1024 + c * 128 + n];
        }
        __syncthreads();

        #pragma unroll 4
        for (int nt = 0; nt < 16; nt++) {
            int n0 = nt * 8;
            int j0 = c * 128 + n0 + 2 * tm4;     // transposed col (o*32+h space)
            // bias (permuted eb2); j0 even so j0 and j0+1 share o-block
            float c0 = __ldg(eb2 + ((j0 & 31) << 5) + (j0 >> 5));
            float c1 = __ldg(eb2 + (((j0 + 1) & 31) << 5) + (j0 >> 5));
            float c2 = c0, c3 = c1;
            #pragma unroll
            for (int ks = 0; ks < 4; ks++) {
                int row = ks * 8 + tm4;
                float b0r = s_B[row * 136 + n0 + td4];
                float b1r = s_B[(row + 4) * 136 + n0 + td4];
                unsigned bh0 = tf32hi(b0r);
                unsigned bh1 = tf32hi(b1r);
                unsigned bl0 = __float_as_uint(b0r - __uint_as_float(bh0));
                unsigned bl1 = __float_as_uint(b1r - __uint_as_float(bh1));
                mma_tf32(c0, c1, c2, c3, Ahi[ks][0], Ahi[ks][1], Ahi[ks][2], Ahi[ks][3], bh0, bh1);
                mma_tf32(c0, c1, c2, c3, Alo[ks][0], Alo[ks][1], Alo[ks][2], Alo[ks][3], bh0, bh1);
                mma_tf32(c0, c1, c2, c3, Ahi[ks][0], Ahi[ks][1], Ahi[ks][2], Ahi[ks][3], bl0, bl1);
            }
            size_t r0 = (size_t)(e0 + ebL + td4);
            *(__half2*)(g_We_h + r0 * 1024 + j0)         = __floats2half2_rn(c0, c1);
            *(__half2*)(g_We_h + (r0 + 8) * 1024 + j0)   = __floats2half2_rn(c2, c3);
        }
    }
}

// ---------------- agg init: agg[b,n,o] = conv_b[o] ----------------------------
__global__ __launch_bounds__(256) void k_agginit(const float* __restrict__ conv_b) {
    int i = blockIdx.x * 256 + threadIdx.x;
    g_agg[i] = __ldg(conv_b + (i & 31));
}

// ---------------- message + scatter (warp per edge, both batches) -------------
// We stored transposed [e][o][h] fp16: lane o reads 32 contiguous halves (64B).
__global__ __launch_bounds__(256) void k_msg(const int* __restrict__ esrc,
                                             const int* __restrict__ edst) {
    int w = blockIdx.x * 8 + (threadIdx.x >> 5);
    int lane = threadIdx.x & 31;
    int src = __ldg(esrc + w);
    int dst = __ldg(edst + w);
    float v0 = g_S[src * 32 + lane];
    float v1 = g_S[(N_NODES + src) * 32 + lane];

    const __half* Wp = g_We_h + (size_t)w * 1024 + lane * 32;
    uint4 q0 = *(const uint4*)(Wp);
    uint4 q1 = *(const uint4*)(Wp + 8);
    uint4 q2 = *(const uint4*)(Wp + 16);
    uint4 q3 = *(const uint4*)(Wp + 24);
    unsigned u[16] = {q0.x, q0.y, q0.z, q0.w, q1.x, q1.y, q1.z, q1.w,
                      q2.x, q2.y, q2.z, q2.w, q3.x, q3.y, q3.z, q3.w};
    float wf[32];
    #pragma unroll
    for (int i = 0; i < 16; i++) {
        float2 f = __half22float2(*(__half2*)&u[i]);
        wf[2 * i] = f.x; wf[2 * i + 1] = f.y;
    }
    float m0 = 0.f, m1 = 0.f;
    #pragma unroll
    for (int h = 0; h < 32; h++) {
        m0 = fmaf(__shfl_sync(0xffffffffu, v0, h), wf[h], m0);
        m1 = fmaf(__shfl_sync(0xffffffffu, v1, h), wf[h], m1);
    }
    atomicAdd(&g_agg[dst * 32 + lane], m0);
    atomicAdd(&g_agg[(N_NODES + dst) * 32 + lane], m1);
}

// ---------------- ReLU + single GRU step (warp per node) ----------------------
__global__ __launch_bounds__(256) void k_gru(const float* __restrict__ wih,
        const float* __restrict__ whh, const float* __restrict__ bih,
        const float* __restrict__ bhh, float* __restrict__ out, int writeOut) {
    __shared__ float s_ih[32 * 96];   // [h][i] transposed
    __shared__ float s_hh[32 * 96];
    int tid = threadIdx.x;
    for (int idx = tid; idx < 3072; idx += 256) {
        int i = idx >> 5, h = idx & 31;
        s_ih[h * 96 + i] = wih[idx];
        s_hh[h * 96 + i] = whh[idx];
    }
    __syncthreads();
    int w = blockIdx.x * 8 + (tid >> 5);   // over 2*N nodes
    int lane = tid & 31;
    float nv = fmaxf(g_agg[w * 32 + lane], 0.f);
    float hv = g_S[w * 32 + lane];
    float gxr = __ldg(bih + lane), gxz = __ldg(bih + 32 + lane), gxn = __ldg(bih + 64 + lane);
    float ghr = __ldg(bhh + lane), ghz = __ldg(bhh + 32 + lane), ghn = __ldg(bhh + 64 + lane);
    #pragma unroll
    for (int h = 0; h < 32; h++) {
        float a = __shfl_sync(0xffffffffu, nv, h);
        float b = __shfl_sync(0xffffffffu, hv, h);
        const float* pi = s_ih + h * 96;
        const float* ph = s_hh + h * 96;
        gxr = fmaf(a, pi[lane], gxr);
        gxz = fmaf(a, pi[32 + lane], gxz);
        gxn = fmaf(a, pi[64 + lane], gxn);
        ghr = fmaf(b, ph[lane], ghr);
        ghz = fmaf(b, ph[32 + lane], ghz);
        ghn = fmaf(b, ph[64 + lane], ghn);
    }
    float r  = 1.f / (1.f + expf(-(gxr + ghr)));
    float z  = 1.f / (1.f + expf(-(gxz + ghz)));
    float nn = tanhf(gxn + r * ghn);
    float newh = (1.f - z) * nn + z * hv;
    g_S[w * 32 + lane] = newh;
    if (writeOut) out[w * 32 + lane] = newh;
}

// ---------------- launch ------------------------------------------------------
extern "C" void kernel_launch(void* const* d_in, const int* in_sizes, int n_in,
                              void* d_out, int out_size) {
    const float* x     = (const float*)d_in[0];
    const float* erel  = (const float*)d_in[1];
    const float* pw1   = (const float*)d_in[2];
    const float* pb1   = (const float*)d_in[3];
    const float* pw2   = (const float*)d_in[4];
    const float* pb2   = (const float*)d_in[5];
    const float* ew1   = (const float*)d_in[6];
    const float* eb1   = (const float*)d_in[7];
    const float* ew2   = (const float*)d_in[8];
    const float* eb2   = (const float*)d_in[9];
    const float* convb = (const float*)d_in[10];
    const float* wih   = (const float*)d_in[11];
    const float* whh   = (const float*)d_in[12];
    const float* bih   = (const float*)d_in[13];
    const float* bhh   = (const float*)d_in[14];
    const int*   esrc  = (const int*)d_in[15];
    const int*   edst  = (const int*)d_in[16];
    float* out = (float*)d_out;

    k_tr<<<32 * 1024 / 256, 256>>>(ew2);
    k_h0<<<2 * N_NODES / 8, 256>>>(x, pw1, pb1, pw2, pb2);
    k_We<<<N_EDGES / 128, 256>>>(erel, ew1, eb1, eb2);
    for (int s = 0; s < 3; s++) {
        k_agginit<<<2 * N_NODES * HID / 256, 256>>>(convb);
        k_msg<<<N_EDGES / 8, 256>>>(esrc, edst);
        k_gru<<<2 * N_NODES / 8, 256>>>(wih, whh, bih, bhh, out, s == 2);
    }
}